// round 2
// baseline (speedup 1.0000x reference)
#include <cuda_runtime.h>
#include <cuda_bf16.h>
#include <cstdint>

#define N_FEAT 256          // IN_F == OUT_F == 256
#define OUT_STRIDE 512      // concat([ft_input, ft_neighbor], axis=1)
#define BM 64
#define BK 32
#define AS_PAD 4

// ---------------------------------------------------------------------------
// Kernel 1: zero the right half of out (ft_neighbor accumulator).
// out is poisoned to 0xAA by the harness.
// ---------------------------------------------------------------------------
__global__ void zero_right_kernel(float* __restrict__ out, int n_nodes) {
    int total = n_nodes * (N_FEAT / 4);
    for (int i = blockIdx.x * blockDim.x + threadIdx.x; i < total;
         i += gridDim.x * blockDim.x) {
        int row = i >> 6;          // / 64
        int q   = i & 63;
        *reinterpret_cast<float4*>(out + (size_t)row * OUT_STRIDE + N_FEAT + q * 4) =
            make_float4(0.f, 0.f, 0.f, 0.f);
    }
}

// ---------------------------------------------------------------------------
// Kernel 2: ft_input = input @ weight, written to out[:, 0:256].
// BM=64 rows x full 256 cols per block, BK=32, 256 threads, 8x8 microtile.
// ---------------------------------------------------------------------------
__global__ __launch_bounds__(256, 2)
void gemm_kernel(const float* __restrict__ A, const float* __restrict__ W,
                 float* __restrict__ out, int n_rows) {
    __shared__ float As[BK][BM + AS_PAD];   // [k][m]
    __shared__ float Ws[BK][N_FEAT];        // [k][n]

    const int tid = threadIdx.x;
    const int ty  = tid >> 5;     // 0..7  -> row group (8 rows each)
    const int tx  = tid & 31;     // 0..31 -> col group (8 cols each)
    const int rowBase = blockIdx.x * BM;

    float acc[8][8];
#pragma unroll
    for (int i = 0; i < 8; i++)
#pragma unroll
        for (int j = 0; j < 8; j++) acc[i][j] = 0.f;

    for (int k0 = 0; k0 < N_FEAT; k0 += BK) {
        // Load A tile: 64 rows x 32 k -> 512 float4, 2 per thread.
#pragma unroll
        for (int it = 0; it < 2; it++) {
            int idx = tid + it * 256;        // 0..511
            int m   = idx >> 3;              // 0..63
            int kq  = (idx & 7) * 4;         // 0,4,...,28
            int gr  = rowBase + m;
            float4 v = make_float4(0.f, 0.f, 0.f, 0.f);
            if (gr < n_rows)
                v = *reinterpret_cast<const float4*>(A + (size_t)gr * N_FEAT + k0 + kq);
            As[kq + 0][m] = v.x;
            As[kq + 1][m] = v.y;
            As[kq + 2][m] = v.z;
            As[kq + 3][m] = v.w;
        }
        // Load W tile: 32 k x 256 n -> 2048 float4, 8 per thread.
#pragma unroll
        for (int it = 0; it < 8; it++) {
            int idx = tid + it * 256;        // 0..2047
            int kk  = idx >> 6;              // 0..31
            int nq  = (idx & 63) * 4;        // 0..252
            *reinterpret_cast<float4*>(&Ws[kk][nq]) =
                *reinterpret_cast<const float4*>(W + (size_t)(k0 + kk) * N_FEAT + nq);
        }
        __syncthreads();

#pragma unroll
        for (int k = 0; k < BK; k++) {
            float af[8], wf[8];
#pragma unroll
            for (int i = 0; i < 8; i++) af[i] = As[k][ty * 8 + i];
#pragma unroll
            for (int j = 0; j < 8; j++) wf[j] = Ws[k][tx * 8 + j];
#pragma unroll
            for (int i = 0; i < 8; i++)
#pragma unroll
                for (int j = 0; j < 8; j++) acc[i][j] += af[i] * wf[j];
        }
        __syncthreads();
    }

    // Store into left half of out (row stride 512).
#pragma unroll
    for (int i = 0; i < 8; i++) {
        int gr = rowBase + ty * 8 + i;
        if (gr < n_rows) {
            float* orow = out + (size_t)gr * OUT_STRIDE + tx * 8;
            *reinterpret_cast<float4*>(orow) =
                make_float4(acc[i][0], acc[i][1], acc[i][2], acc[i][3]);
            *reinterpret_cast<float4*>(orow + 4) =
                make_float4(acc[i][4], acc[i][5], acc[i][6], acc[i][7]);
        }
    }
}

// ---------------------------------------------------------------------------
// Kernel 3: out[dst, 256:512] += val * out[src, 0:256]   (one warp per edge)
// Uses red.global.add.v4.f32 (sm_90+) for vectorized non-returning atomics.
// NOTE: edge indices are int32 on device (harness materializes int64 as i32).
// ---------------------------------------------------------------------------
__global__ __launch_bounds__(256)
void scatter_kernel(const int* __restrict__ esrc,
                    const int* __restrict__ edst,
                    const float* __restrict__ eval_,
                    float* __restrict__ out, int n_edges) {
    int e    = (blockIdx.x * blockDim.x + threadIdx.x) >> 5;
    int lane = threadIdx.x & 31;
    if (e >= n_edges) return;

    int   s = __ldg(&esrc[e]);
    int   d = __ldg(&edst[e]);
    float v = __ldg(&eval_[e]);

    const float4* srow = reinterpret_cast<const float4*>(out + (size_t)s * OUT_STRIDE);
    float* dbase = out + (size_t)d * OUT_STRIDE + N_FEAT + lane * 8;

    float4 a = srow[lane * 2];
    float4 b = srow[lane * 2 + 1];
    a.x *= v; a.y *= v; a.z *= v; a.w *= v;
    b.x *= v; b.y *= v; b.z *= v; b.w *= v;

    asm volatile("red.global.add.v4.f32 [%0], {%1,%2,%3,%4};"
                 :: "l"(dbase), "f"(a.x), "f"(a.y), "f"(a.z), "f"(a.w)
                 : "memory");
    asm volatile("red.global.add.v4.f32 [%0], {%1,%2,%3,%4};"
                 :: "l"(dbase + 4), "f"(b.x), "f"(b.y), "f"(b.z), "f"(b.w)
                 : "memory");
}

// ---------------------------------------------------------------------------
// Launch
// inputs: [0] input_ (f32, N*256)  [1] edge_src (i32 on device, E)
//         [2] edge_dst (i32, E)    [3] edge_val (f32, E)  [4] weight (f32, 256*256)
// output: f32, N*512
// ---------------------------------------------------------------------------
extern "C" void kernel_launch(void* const* d_in, const int* in_sizes, int n_in,
                              void* d_out, int out_size) {
    const float* input_   = (const float*)d_in[0];
    const int*   edge_src = (const int*)d_in[1];
    const int*   edge_dst = (const int*)d_in[2];
    const float* edge_val = (const float*)d_in[3];
    const float* weight   = (const float*)d_in[4];
    float*       out      = (float*)d_out;

    const int n_nodes = in_sizes[0] / N_FEAT;
    const int n_edges = in_sizes[1];

    // 1) zero ft_neighbor accumulator region
    zero_right_kernel<<<2048, 256>>>(out, n_nodes);

    // 2) ft_input = input @ weight  -> out[:, 0:256]
    int gemm_blocks = (n_nodes + BM - 1) / BM;
    gemm_kernel<<<gemm_blocks, 256>>>(input_, weight, out, n_nodes);

    // 3) scatter-add: out[dst, 256:512] += val * out[src, 0:256]
    int blocks = (n_edges * 32 + 255) / 256;
    scatter_kernel<<<blocks, 256>>>(edge_src, edge_dst, edge_val, out, n_edges);
}

// round 3
// speedup vs baseline: 3.0442x; 3.0442x over previous
#include <cuda_runtime.h>
#include <cuda_bf16.h>
#include <cstdint>

#define N_FEAT 256          // IN_F == OUT_F == 256
#define OUT_STRIDE 512      // concat([ft_input, ft_neighbor], axis=1)
#define BM 64
#define BK 32
#define AS_PAD 4

#define MAX_NODES 100000
#define MAX_EDGES 3200000
#define SCAN_BLK 1024
#define MAX_SCAN_BLOCKS ((MAX_NODES + SCAN_BLK - 1) / SCAN_BLK)   // 98

// ---------------------------------------------------------------------------
// Scratch (device globals: the allowed allocation-free scratch path)
// ---------------------------------------------------------------------------
__device__ int   d_cursor[MAX_NODES];          // histogram counts, then write cursor
__device__ int   d_rowstart[MAX_NODES + 1];    // CSR row offsets
__device__ int   d_blocksum[MAX_SCAN_BLOCKS];
__device__ int   d_srcsorted[MAX_EDGES];       // src ids sorted by dst
__device__ float d_valsorted[MAX_EDGES];       // edge vals sorted by dst

// ---------------------------------------------------------------------------
// Kernel 0: zero histogram counters
// ---------------------------------------------------------------------------
__global__ void zero_count_kernel(int n_nodes) {
    int i = blockIdx.x * blockDim.x + threadIdx.x;
    if (i < n_nodes) d_cursor[i] = 0;
}

// ---------------------------------------------------------------------------
// Kernel 1: histogram of edge_dst
// ---------------------------------------------------------------------------
__global__ void hist_kernel(const int* __restrict__ edst, int n_edges) {
    int e = blockIdx.x * blockDim.x + threadIdx.x;
    if (e < n_edges) atomicAdd(&d_cursor[edst[e]], 1);
}

// ---------------------------------------------------------------------------
// Kernels 2a/2b/2c: exclusive scan of counts -> d_rowstart
// ---------------------------------------------------------------------------
__global__ __launch_bounds__(SCAN_BLK)
void scan1_kernel(int n_nodes) {
    __shared__ int tmp[SCAN_BLK];
    int tid = threadIdx.x;
    int i   = blockIdx.x * SCAN_BLK + tid;
    int v   = (i < n_nodes) ? d_cursor[i] : 0;
    tmp[tid] = v;
    __syncthreads();
#pragma unroll
    for (int off = 1; off < SCAN_BLK; off <<= 1) {
        int t = (tid >= off) ? tmp[tid - off] : 0;
        __syncthreads();
        tmp[tid] += t;
        __syncthreads();
    }
    if (i < n_nodes) d_rowstart[i] = tmp[tid] - v;           // block-local exclusive
    if (tid == SCAN_BLK - 1) d_blocksum[blockIdx.x] = tmp[tid];
}

__global__ void scan2_kernel(int n_blocks) {
    __shared__ int tmp[128];
    int tid = threadIdx.x;
    int v   = (tid < n_blocks) ? d_blocksum[tid] : 0;
    tmp[tid] = v;
    __syncthreads();
#pragma unroll
    for (int off = 1; off < 128; off <<= 1) {
        int t = (tid >= off) ? tmp[tid - off] : 0;
        __syncthreads();
        tmp[tid] += t;
        __syncthreads();
    }
    if (tid < n_blocks) d_blocksum[tid] = tmp[tid] - v;      // exclusive
}

__global__ void scan3_kernel(int n_nodes, int n_edges) {
    int i = blockIdx.x * blockDim.x + threadIdx.x;
    if (i < n_nodes) {
        int g = d_rowstart[i] + d_blocksum[i / SCAN_BLK];
        d_rowstart[i] = g;
        d_cursor[i]   = g;                                    // write cursor
    }
    if (i == 0) d_rowstart[n_nodes] = n_edges;
}

// ---------------------------------------------------------------------------
// Kernel 3: reorder (src, val) by dst
// ---------------------------------------------------------------------------
__global__ void reorder_kernel(const int* __restrict__ esrc,
                               const int* __restrict__ edst,
                               const float* __restrict__ eval_, int n_edges) {
    int e = blockIdx.x * blockDim.x + threadIdx.x;
    if (e >= n_edges) return;
    int pos = atomicAdd(&d_cursor[edst[e]], 1);
    d_srcsorted[pos] = esrc[e];
    d_valsorted[pos] = eval_[e];
}

// ---------------------------------------------------------------------------
// Kernel 4: ft_input = input @ weight, written to out[:, 0:256].
// ---------------------------------------------------------------------------
__global__ __launch_bounds__(256, 2)
void gemm_kernel(const float* __restrict__ A, const float* __restrict__ W,
                 float* __restrict__ out, int n_rows) {
    __shared__ float As[BK][BM + AS_PAD];   // [k][m]
    __shared__ float Ws[BK][N_FEAT];        // [k][n]

    const int tid = threadIdx.x;
    const int ty  = tid >> 5;
    const int tx  = tid & 31;
    const int rowBase = blockIdx.x * BM;

    float acc[8][8];
#pragma unroll
    for (int i = 0; i < 8; i++)
#pragma unroll
        for (int j = 0; j < 8; j++) acc[i][j] = 0.f;

    for (int k0 = 0; k0 < N_FEAT; k0 += BK) {
#pragma unroll
        for (int it = 0; it < 2; it++) {
            int idx = tid + it * 256;
            int m   = idx >> 3;
            int kq  = (idx & 7) * 4;
            int gr  = rowBase + m;
            float4 v = make_float4(0.f, 0.f, 0.f, 0.f);
            if (gr < n_rows)
                v = *reinterpret_cast<const float4*>(A + (size_t)gr * N_FEAT + k0 + kq);
            As[kq + 0][m] = v.x;
            As[kq + 1][m] = v.y;
            As[kq + 2][m] = v.z;
            As[kq + 3][m] = v.w;
        }
#pragma unroll
        for (int it = 0; it < 8; it++) {
            int idx = tid + it * 256;
            int kk  = idx >> 6;
            int nq  = (idx & 63) * 4;
            *reinterpret_cast<float4*>(&Ws[kk][nq]) =
                *reinterpret_cast<const float4*>(W + (size_t)(k0 + kk) * N_FEAT + nq);
        }
        __syncthreads();

#pragma unroll
        for (int k = 0; k < BK; k++) {
            float af[8], wf[8];
#pragma unroll
            for (int i = 0; i < 8; i++) af[i] = As[k][ty * 8 + i];
#pragma unroll
            for (int j = 0; j < 8; j++) wf[j] = Ws[k][tx * 8 + j];
#pragma unroll
            for (int i = 0; i < 8; i++)
#pragma unroll
                for (int j = 0; j < 8; j++) acc[i][j] += af[i] * wf[j];
        }
        __syncthreads();
    }

#pragma unroll
    for (int i = 0; i < 8; i++) {
        int gr = rowBase + ty * 8 + i;
        if (gr < n_rows) {
            float* orow = out + (size_t)gr * OUT_STRIDE + tx * 8;
            *reinterpret_cast<float4*>(orow) =
                make_float4(acc[i][0], acc[i][1], acc[i][2], acc[i][3]);
            *reinterpret_cast<float4*>(orow + 4) =
                make_float4(acc[i][4], acc[i][5], acc[i][6], acc[i][7]);
        }
    }
}

// ---------------------------------------------------------------------------
// Kernel 5: per-dst accumulate. One warp per dst node, no atomics.
// out[dst, 256:512] = sum_{e in CSR[dst]} val_e * out[src_e, 0:256]
// Also covers the zero-init of the right half (empty rows write zeros).
// ---------------------------------------------------------------------------
__global__ __launch_bounds__(256)
void accumulate_kernel(float* __restrict__ out, int n_nodes) {
    int w    = (blockIdx.x * blockDim.x + threadIdx.x) >> 5;
    int lane = threadIdx.x & 31;
    if (w >= n_nodes) return;

    int beg = d_rowstart[w];
    int end = d_rowstart[w + 1];

    float acc[8];
#pragma unroll
    for (int i = 0; i < 8; i++) acc[i] = 0.f;

    int i = beg;
    for (; i + 1 < end; i += 2) {
        int   s0 = __ldg(&d_srcsorted[i]);
        float v0 = __ldg(&d_valsorted[i]);
        int   s1 = __ldg(&d_srcsorted[i + 1]);
        float v1 = __ldg(&d_valsorted[i + 1]);
        const float4* p0 = reinterpret_cast<const float4*>(out + (size_t)s0 * OUT_STRIDE + lane * 8);
        const float4* p1 = reinterpret_cast<const float4*>(out + (size_t)s1 * OUT_STRIDE + lane * 8);
        float4 a0 = __ldg(p0), b0 = __ldg(p0 + 1);
        float4 a1 = __ldg(p1), b1 = __ldg(p1 + 1);
        acc[0] += v0 * a0.x; acc[1] += v0 * a0.y; acc[2] += v0 * a0.z; acc[3] += v0 * a0.w;
        acc[4] += v0 * b0.x; acc[5] += v0 * b0.y; acc[6] += v0 * b0.z; acc[7] += v0 * b0.w;
        acc[0] += v1 * a1.x; acc[1] += v1 * a1.y; acc[2] += v1 * a1.z; acc[3] += v1 * a1.w;
        acc[4] += v1 * b1.x; acc[5] += v1 * b1.y; acc[6] += v1 * b1.z; acc[7] += v1 * b1.w;
    }
    if (i < end) {
        int   s0 = __ldg(&d_srcsorted[i]);
        float v0 = __ldg(&d_valsorted[i]);
        const float4* p0 = reinterpret_cast<const float4*>(out + (size_t)s0 * OUT_STRIDE + lane * 8);
        float4 a0 = __ldg(p0), b0 = __ldg(p0 + 1);
        acc[0] += v0 * a0.x; acc[1] += v0 * a0.y; acc[2] += v0 * a0.z; acc[3] += v0 * a0.w;
        acc[4] += v0 * b0.x; acc[5] += v0 * b0.y; acc[6] += v0 * b0.z; acc[7] += v0 * b0.w;
    }

    float* o = out + (size_t)w * OUT_STRIDE + N_FEAT + lane * 8;
    *reinterpret_cast<float4*>(o)     = make_float4(acc[0], acc[1], acc[2], acc[3]);
    *reinterpret_cast<float4*>(o + 4) = make_float4(acc[4], acc[5], acc[6], acc[7]);
}

// ---------------------------------------------------------------------------
// Launch
// ---------------------------------------------------------------------------
extern "C" void kernel_launch(void* const* d_in, const int* in_sizes, int n_in,
                              void* d_out, int out_size) {
    const float* input_   = (const float*)d_in[0];
    const int*   edge_src = (const int*)d_in[1];
    const int*   edge_dst = (const int*)d_in[2];
    const float* edge_val = (const float*)d_in[3];
    const float* weight   = (const float*)d_in[4];
    float*       out      = (float*)d_out;

    const int n_nodes = in_sizes[0] / N_FEAT;
    const int n_edges = in_sizes[1];

    const int eb = (n_edges + 255) / 256;
    const int nb = (n_nodes + 255) / 256;
    const int scan_blocks = (n_nodes + SCAN_BLK - 1) / SCAN_BLK;

    // CSR build
    zero_count_kernel<<<nb, 256>>>(n_nodes);
    hist_kernel<<<eb, 256>>>(edge_dst, n_edges);
    scan1_kernel<<<scan_blocks, SCAN_BLK>>>(n_nodes);
    scan2_kernel<<<1, 128>>>(scan_blocks);
    scan3_kernel<<<nb, 256>>>(n_nodes, n_edges);
    reorder_kernel<<<eb, 256>>>(edge_src, edge_dst, edge_val, n_edges);

    // ft_input = input @ weight  -> out[:, 0:256]
    int gemm_blocks = (n_nodes + BM - 1) / BM;
    gemm_kernel<<<gemm_blocks, 256>>>(input_, weight, out, n_nodes);

    // ft_neighbor = A @ ft_input -> out[:, 256:512]  (one warp per dst)
    int acc_blocks = (n_nodes * 32 + 255) / 256;
    accumulate_kernel<<<acc_blocks, 256>>>(out, n_nodes);
}